// round 1
// baseline (speedup 1.0000x reference)
#include <cuda_runtime.h>
#include <cstdint>

// ---------------- problem constants (from reference) ----------------
#define NPTS_MAX 500000
#define BATCH 2
#define CZ 1
#define CY 400
#define CX 352
#define CL (BATCH * CZ * CY * CX)   // 281600
#define C_H 64
#define C_IN 11

__device__ __constant__ float VXc = 0.2f, VYc = 0.2f, VZc = 4.0f;
__device__ __constant__ float XOFFc = 0.1f;      // VX/2 + X0
__device__ __constant__ float YOFFc = -39.9f;    // VY/2 + Y0
__device__ __constant__ float ZOFFc = -1.0f;     // VZ/2 + Z0

// ---------------- scratch (static device globals; no allocs) ----------------
__device__ float g_pf1[(size_t)C_H * NPTS_MAX];     // column-major [64][N], 128MB
__device__ float g_vmax1[(size_t)CL * C_H];         // 72MB
__device__ float g_vsum[(size_t)CL * 3];
__device__ int   g_cnt[CL];

// ---------------- K0: zero scratch + output ----------------
__global__ void k_zero(float* __restrict__ out)
{
    const int total = CL * C_H;  // 18,022,400
    for (int i = blockIdx.x * blockDim.x + threadIdx.x; i < total;
         i += gridDim.x * blockDim.x) {
        g_vmax1[i] = 0.0f;
        out[i] = 0.0f;
        if (i < CL * 3) g_vsum[i] = 0.0f;
        if (i < CL)     g_cnt[i] = 0;
    }
}

// ---------------- K1: per-voxel count + xyz sum ----------------
__global__ void k_sums(const float* __restrict__ features,
                       const int* __restrict__ coors, int n)
{
    int i = blockIdx.x * blockDim.x + threadIdx.x;
    if (i >= n) return;
    int b = coors[4 * i + 0];
    int z = coors[4 * i + 1];
    int y = coors[4 * i + 2];
    int x = coors[4 * i + 3];
    int idx = ((b * CZ + z) * CY + y) * CX + x;
    atomicAdd(&g_cnt[idx], 1);
    atomicAdd(&g_vsum[3 * idx + 0], features[4 * i + 0]);
    atomicAdd(&g_vsum[3 * idx + 1], features[4 * i + 1]);
    atomicAdd(&g_vsum[3 * idx + 2], features[4 * i + 2]);
}

// ---------------- K2: feats -> GEMM1 -> relu -> store pf1 + segmax vmax1 ----------------
__global__ void __launch_bounds__(128)
k_pf1(const float* __restrict__ features, const int* __restrict__ coors,
      const float* __restrict__ W1, const float* __restrict__ scale1,
      const float* __restrict__ shift1, int n)
{
    __shared__ float sW1[C_IN][C_H];
    __shared__ float sSc[C_H], sSh[C_H];
    for (int t = threadIdx.x; t < C_IN * C_H; t += blockDim.x)
        sW1[t / C_H][t % C_H] = W1[t];
    if (threadIdx.x < C_H) {
        sSc[threadIdx.x] = scale1[threadIdx.x];
        sSh[threadIdx.x] = shift1[threadIdx.x];
    }
    __syncthreads();

    int i = blockIdx.x * blockDim.x + threadIdx.x;
    if (i >= n) return;

    int b = coors[4 * i + 0];
    int z = coors[4 * i + 1];
    int y = coors[4 * i + 2];
    int x = coors[4 * i + 3];
    int idx = ((b * CZ + z) * CY + y) * CX + x;

    float f0 = features[4 * i + 0];
    float f1 = features[4 * i + 1];
    float f2 = features[4 * i + 2];
    float f3 = features[4 * i + 3];

    float inv = 1.0f / fmaxf((float)g_cnt[idx], 1.0f);
    float mx = g_vsum[3 * idx + 0] * inv;
    float my = g_vsum[3 * idx + 1] * inv;
    float mz = g_vsum[3 * idx + 2] * inv;

    float feats[C_IN];
    feats[0] = f0; feats[1] = f1; feats[2] = f2; feats[3] = f3;
    feats[4] = f0 - mx; feats[5] = f1 - my; feats[6] = f2 - mz;
    feats[7] = f0 - ((float)x * VXc + XOFFc);
    feats[8] = f1 - ((float)y * VYc + YOFFc);
    feats[9] = f2 - ((float)z * VZc + ZOFFc);
    feats[10] = sqrtf(f0 * f0 + f1 * f1 + f2 * f2);

    float acc[C_H];
#pragma unroll
    for (int j = 0; j < C_H; j++) acc[j] = 0.0f;
#pragma unroll
    for (int k = 0; k < C_IN; k++) {
        float fk = feats[k];
#pragma unroll
        for (int j = 0; j < C_H; j++)
            acc[j] = fmaf(fk, sW1[k][j], acc[j]);
    }

    const size_t base = (size_t)idx * C_H;
#pragma unroll
    for (int j = 0; j < C_H; j++) {
        float v = fmaxf(fmaf(acc[j], sSc[j], sSh[j]), 0.0f);
        g_pf1[(size_t)j * n + i] = v;
        if (v > 0.0f)
            atomicMax((int*)&g_vmax1[base + j], __float_as_int(v));
    }
}

// ---------------- K3: concat(pf1, vmax1[idx]) -> GEMM2 -> relu -> segmax out ----------------
__global__ void __launch_bounds__(128)
k_pf2(const int* __restrict__ coors, const float* __restrict__ W2,
      const float* __restrict__ scale2, const float* __restrict__ shift2,
      float* __restrict__ out, int n)
{
    __shared__ float sW2[2 * C_H][C_H];   // 32KB
    __shared__ float sSc[C_H], sSh[C_H];
    for (int t = threadIdx.x; t < 2 * C_H * C_H; t += blockDim.x)
        sW2[t / C_H][t % C_H] = W2[t];
    if (threadIdx.x < C_H) {
        sSc[threadIdx.x] = scale2[threadIdx.x];
        sSh[threadIdx.x] = shift2[threadIdx.x];
    }
    __syncthreads();

    int i = blockIdx.x * blockDim.x + threadIdx.x;
    if (i >= n) return;

    int b = coors[4 * i + 0];
    int z = coors[4 * i + 1];
    int y = coors[4 * i + 2];
    int x = coors[4 * i + 3];
    int idx = ((b * CZ + z) * CY + y) * CX + x;
    const size_t base = (size_t)idx * C_H;

    float acc[C_H];
#pragma unroll
    for (int j = 0; j < C_H; j++) acc[j] = 0.0f;

#pragma unroll 1
    for (int k = 0; k < C_H; k++) {
        float p = g_pf1[(size_t)k * n + i];
#pragma unroll
        for (int j = 0; j < C_H; j++)
            acc[j] = fmaf(p, sW2[k][j], acc[j]);
    }
#pragma unroll 1
    for (int k = 0; k < C_H; k++) {
        float m = g_vmax1[base + k];
#pragma unroll
        for (int j = 0; j < C_H; j++)
            acc[j] = fmaf(m, sW2[C_H + k][j], acc[j]);
    }

#pragma unroll
    for (int j = 0; j < C_H; j++) {
        float v = fmaxf(fmaf(acc[j], sSc[j], sSh[j]), 0.0f);
        if (v > 0.0f)
            atomicMax((int*)&out[base + j], __float_as_int(v));
    }
}

// ---------------- launch ----------------
extern "C" void kernel_launch(void* const* d_in, const int* in_sizes, int n_in,
                              void* d_out, int out_size)
{
    const float* features = (const float*)d_in[0];
    const int*   coors    = (const int*)d_in[1];
    const float* W1       = (const float*)d_in[2];
    const float* scale1   = (const float*)d_in[3];
    const float* shift1   = (const float*)d_in[4];
    const float* W2       = (const float*)d_in[5];
    const float* scale2   = (const float*)d_in[6];
    const float* shift2   = (const float*)d_in[7];
    float* out = (float*)d_out;

    int n = in_sizes[0] / 4;   // N points

    k_zero<<<592, 256>>>(out);                       // 592*256*~119 ≈ covers 18M grid-stride
    k_sums<<<(n + 255) / 256, 256>>>(features, coors, n);
    k_pf1<<<(n + 127) / 128, 128>>>(features, coors, W1, scale1, shift1, n);
    k_pf2<<<(n + 127) / 128, 128>>>(coors, W2, scale2, shift2, out, n);
}